// round 5
// baseline (speedup 1.0000x reference)
#include <cuda_runtime.h>
#include <cuda_bf16.h>
#include <cstdint>

// QRegulariser: out = mean_b( 1 - prod_q cos^2( (hidden@W.T + b)_q / 2 ) )
// B=65536, H=1024, Q=8. HBM-bound: 256 MB of hidden.
//
// R5 vs R4 (53.4us, DRAM 64%, issue 46%, 16 warps):
//  - 28 warps/SM (896 thr), RPW=4: regs 120->~65, 7 warps/SMSP for latency
//    hiding (R4's limiter was per-warp dependency exposure, not MLP).
//  - work = 16384 row-groups over 4144 warps = 3.953/4 -> 98.8% balance.
//  - same per-warp cp.async (LDGSTS) ring: NBUF=3, lookahead 2 chunks,
//    112KB/SM in flight. smem 168KB h + 32KB W.

#define HDIM 1024
#define QDIM 8
#define RPW 4
#define WPB 28
#define NTHREADS (WPB * 32)          // 896
#define GRID_SMS 148
#define TOTAL_WARPS (GRID_SMS * WPB) // 4144
#define NCHUNK 8                     // 8 chunks of 512B per row
#define WARP_STAGE (RPW * 512)       // 2048 B per warp per buffer
#define NBUF 3
#define SW_BYTES (QDIM * HDIM * 4)   // 32 KB
#define HBUF_BYTES (WPB * NBUF * WARP_STAGE)  // 172032
#define DSMEM_BYTES (SW_BYTES + HBUF_BYTES)   // 204800

__device__ double g_partials[GRID_SMS];
__device__ unsigned int g_counter = 0;

__device__ __forceinline__ uint32_t swz(uint32_t off) {
    return off ^ ((off >> 3) & 0x70u);
}
__device__ __forceinline__ unsigned long long fma2(unsigned long long a,
                                                   unsigned long long b,
                                                   unsigned long long c) {
    unsigned long long d;
    asm("fma.rn.f32x2 %0, %1, %2, %3;" : "=l"(d) : "l"(a), "l"(b), "l"(c));
    return d;
}
__device__ __forceinline__ unsigned long long add2(unsigned long long a,
                                                   unsigned long long b) {
    unsigned long long d;
    asm("add.rn.f32x2 %0, %1, %2;" : "=l"(d) : "l"(a), "l"(b));
    return d;
}
__device__ __forceinline__ unsigned long long packff(float x) {
    unsigned long long d;
    asm("mov.b64 %0, {%1, %1};" : "=l"(d) : "f"(x));
    return d;
}
__device__ __forceinline__ float2 unpack2(unsigned long long v) {
    float2 r;
    asm("mov.b64 {%0, %1}, %2;" : "=f"(r.x), "=f"(r.y) : "l"(v));
    return r;
}
__device__ __forceinline__ void cp16(uint32_t dst_smem, const void* src) {
    asm volatile("cp.async.cg.shared.global [%0], [%1], 16;"
                 :: "r"(dst_smem), "l"(src) : "memory");
}
__device__ __forceinline__ void sts_zero16(uint32_t dst_smem) {
    asm volatile("st.shared.v4.u32 [%0], {%1, %1, %1, %1};"
                 :: "r"(dst_smem), "r"(0u) : "memory");
}
__device__ __forceinline__ void cp_commit() {
    asm volatile("cp.async.commit_group;" ::: "memory");
}
__device__ __forceinline__ void cp_wait1() {
    asm volatile("cp.async.wait_group 1;" ::: "memory");
}

__global__ __launch_bounds__(NTHREADS, 1)
void qreg_main_kernel(const float* __restrict__ hidden,
                      const float* __restrict__ Wm,
                      const float* __restrict__ bv,
                      float* __restrict__ out,
                      int B) {
    extern __shared__ __align__(128) char dsm[];
    char* sW = dsm;                  // 32 KB swizzled W^T
    char* hbuf = dsm + SW_BYTES;     // 168 KB h staging
    __shared__ float sB[QDIM];
    __shared__ double warp_sums[WPB];
    __shared__ unsigned int is_last;

    const int tid = threadIdx.x;
    const int bid = blockIdx.x;

    // Build swizzled W^T: column c gets 32B (q0..q7) at off = c*32 + q*4.
    for (int i = tid; i < QDIM * HDIM / 4; i += NTHREADS) {
        const float4 v = reinterpret_cast<const float4*>(Wm)[i];
        const int q = (i * 4) / HDIM;
        const int c = (i * 4) % HDIM;
        const float vv[4] = {v.x, v.y, v.z, v.w};
        #pragma unroll
        for (int j = 0; j < 4; ++j) {
            const uint32_t off = swz((uint32_t)(c + j) * 32u + (uint32_t)q * 4u);
            *reinterpret_cast<float*>(sW + off) = vv[j];
        }
    }
    if (tid < QDIM) sB[tid] = bv[tid];
    __syncthreads();

    const int warp = tid >> 5;
    const int lane = tid & 31;
    const int gw = bid * WPB + warp;         // global warp id
    const int ntasks = (B + RPW - 1) / RPW;  // row-groups of 4

    // Per-warp staging (each lane only touches its own 16B column).
    const uint32_t mybuf =
        (uint32_t)__cvta_generic_to_shared(hbuf) +
        (uint32_t)warp * (NBUF * WARP_STAGE) + (uint32_t)lane * 16u;
    char* mybuf_g = hbuf + warp * (NBUF * WARP_STAGE) + lane * 16;
    const char* hbase = (const char*)hidden + (size_t)lane * 16u;

    int nmy = 0;
    if (gw < ntasks) nmy = (ntasks - 1 - gw) / TOTAL_WARPS + 1;
    const int nchunks = nmy * NCHUNK;

    double local = 0.0;

    if (nchunks > 0) {
        auto issue_chunk = [&](int c) {
            const int k = c >> 3;               // local group index
            const int it = c & 7;               // chunk within group
            const int t = gw + k * TOTAL_WARPS; // global row-group
            const int row0 = t * RPW;
            const uint32_t dst = mybuf + (uint32_t)(c % NBUF) * WARP_STAGE;
            const char* src = hbase + (size_t)row0 * 4096u + (size_t)it * 512u;
            if (row0 + RPW <= B) {
                #pragma unroll
                for (int r = 0; r < RPW; ++r)
                    cp16(dst + r * 512u, src + (size_t)r * 4096u);
            } else {
                #pragma unroll
                for (int r = 0; r < RPW; ++r) {
                    if (row0 + r < B) cp16(dst + r * 512u, src + (size_t)r * 4096u);
                    else              sts_zero16(dst + r * 512u);
                }
            }
        };

        issue_chunk(0); cp_commit();
        if (nchunks > 1) issue_chunk(1);
        cp_commit();

        unsigned long long acc[RPW][4];
        #pragma unroll
        for (int r = 0; r < RPW; ++r)
            #pragma unroll
            for (int qp = 0; qp < 4; ++qp) acc[r][qp] = 0ull;

        for (int c = 0; c < nchunks; ++c) {
            cp_wait1();                         // chunk c resident
            if (c + 2 < nchunks) issue_chunk(c + 2);
            cp_commit();

            const int it = c & 7;
            const char* buf = mybuf_g + (c % NBUF) * WARP_STAGE;

            float4 h[RPW];
            #pragma unroll
            for (int r = 0; r < RPW; ++r)
                h[r] = *reinterpret_cast<const float4*>(buf + r * 512);

            const int col4 = it * 32 + lane;
            #pragma unroll
            for (int j = 0; j < 4; ++j) {
                const uint32_t base = (uint32_t)col4 * 128u + (uint32_t)j * 32u;
                const ulonglong2 wA =
                    *reinterpret_cast<const ulonglong2*>(sW + swz(base));
                const ulonglong2 wB =
                    *reinterpret_cast<const ulonglong2*>(sW + swz(base + 16u));
                #pragma unroll
                for (int r = 0; r < RPW; ++r) {
                    const float* hp = &h[r].x;
                    const unsigned long long hh = packff(hp[j]);
                    acc[r][0] = fma2(hh, wA.x, acc[r][0]);
                    acc[r][1] = fma2(hh, wA.y, acc[r][1]);
                    acc[r][2] = fma2(hh, wB.x, acc[r][2]);
                    acc[r][3] = fma2(hh, wB.y, acc[r][3]);
                }
            }

            if (it == NCHUNK - 1) {
                // Group done: butterfly-reduce accs across the warp.
                #pragma unroll
                for (int r = 0; r < RPW; ++r) {
                    #pragma unroll
                    for (int qp = 0; qp < 4; ++qp) {
                        unsigned long long v = acc[r][qp];
                        #pragma unroll
                        for (int d = 16; d > 0; d >>= 1)
                            v = add2(v, __shfl_xor_sync(0xffffffffu, v, d));
                        acc[r][qp] = v;
                    }
                }
                const int t = gw + (c >> 3) * TOTAL_WARPS;
                const int row0 = t * RPW;
                #pragma unroll
                for (int r = 0; r < RPW; ++r) {
                    if (row0 + r >= B) continue;
                    float pr = 1.0f;
                    #pragma unroll
                    for (int qp = 0; qp < 4; ++qp) {
                        const float2 th = unpack2(acc[r][qp]);
                        const float t0 = th.x + sB[2 * qp];
                        const float t1 = th.y + sB[2 * qp + 1];
                        pr *= 0.25f * (1.0f + __cosf(t0)) * (1.0f + __cosf(t1));
                    }
                    local += (double)(1.0f - pr);
                }
                #pragma unroll
                for (int r = 0; r < RPW; ++r)
                    #pragma unroll
                    for (int qp = 0; qp < 4; ++qp) acc[r][qp] = 0ull;
            }
        }
    }

    if (lane == 0) warp_sums[warp] = local;
    __syncthreads();

    if (tid == 0) {
        double s = 0.0;
        #pragma unroll
        for (int w = 0; w < WPB; ++w) s += warp_sums[w];
        g_partials[bid] = s;
        __threadfence();
        const unsigned int prev = atomicAdd(&g_counter, 1u);
        is_last = (prev == gridDim.x - 1) ? 1u : 0u;
    }
    __syncthreads();

    if (is_last) {
        __threadfence();
        const volatile double* vp = g_partials;
        double s = 0.0;
        for (int i = tid; i < (int)gridDim.x; i += NTHREADS) s += vp[i];
        #pragma unroll
        for (int d = 16; d > 0; d >>= 1)
            s += __shfl_down_sync(0xffffffffu, s, d);
        if (lane == 0) warp_sums[warp] = s;
        __syncthreads();
        if (tid == 0) {
            double tsum = 0.0;
            #pragma unroll
            for (int w = 0; w < WPB; ++w) tsum += warp_sums[w];
            out[0] = (float)(tsum / (double)B);
            g_counter = 0;  // reset for graph replay
        }
    }
}

extern "C" void kernel_launch(void* const* d_in, const int* in_sizes, int n_in,
                              void* d_out, int out_size) {
    const float* hidden = (const float*)d_in[0];   // [B, H] f32
    const float* Wm     = (const float*)d_in[1];   // [Q, H] f32
    const float* bv     = (const float*)d_in[2];   // [Q]    f32
    float* out = (float*)d_out;

    const int B = in_sizes[0] / HDIM;

    static bool attr_set = false;
    if (!attr_set) {
        cudaFuncSetAttribute(qreg_main_kernel,
                             cudaFuncAttributeMaxDynamicSharedMemorySize,
                             DSMEM_BYTES);
        attr_set = true;
    }

    qreg_main_kernel<<<GRID_SMS, NTHREADS, DSMEM_BYTES>>>(hidden, Wm, bv, out, B);
}